// round 11
// baseline (speedup 1.0000x reference)
#include <cuda_runtime.h>
#include <math_constants.h>

// SoftmaxTreeWithLoss on GB300 (sm_103a).
// x: [N=16, C=4096, H=26, W=26] f32; label: [N,26,26] i32 in [0,C)
// Tree: group 0 = channels [0,512) (roots); then 512 groups of 7 children.
// loss_pos = -( child-group logps + x[root] - LSE(root group) ).
//
// R10: concurrency comes from WARP COUNT, not per-warp batching (R7/R9 showed
// per-warp MLP is pinned at ~2 regardless of source structure). R6 skeleton
// with 16 streaming warps x 32 channels (was 8 x 64) + 1 chain warp = 544
// threads. Grid 338 x ~2.3 CTAs/SM resident -> ~39 warps/SM streaming.

#define HW_SZ 676              // 26*26
#define CN 4096
#define POS_PER_BLOCK 32
#define NW_STREAM 16
#define CH_PER_WARP 32         // 512 / 16
#define THREADS 544            // 16 stream + 1 chain warp

__global__ __launch_bounds__(THREADS, 2)
void tree_loss_kernel(const float* __restrict__ x,
                      const int*   __restrict__ label,
                      const int*   __restrict__ group_offsets,
                      const int*   __restrict__ group_sizes,
                      const int*   __restrict__ cid_groups,
                      const int*   __restrict__ parents,
                      float* __restrict__ out,
                      int M, float inv_norm)
{
    __shared__ float sm_s[NW_STREAM][POS_PER_BLOCK];

    const int lane = threadIdx.x & 31;
    const int w    = threadIdx.x >> 5;
    const int pos  = blockIdx.x * POS_PER_BLOCK + lane;
    const bool valid = pos < M;

    const int n  = valid ? (pos / HW_SZ) : 0;
    const int hw = valid ? (pos - n * HW_SZ) : 0;
    const float* base = x + (size_t)n * (CN * HW_SZ) + hw;

    if (w < NW_STREAM) {
        // ---- streaming warp: 32 root channels for this lane's position ----
        const int c0 = w * CH_PER_WARP;
        float a0 = 0.f, a1 = 0.f, a2 = 0.f, a3 = 0.f;
        if (valid) {
            const float* p = base + (size_t)c0 * HW_SZ;
            #pragma unroll
            for (int b = 0; b < CH_PER_WARP / 8; b++) {
                // 8 independent read-once loads (streaming hint), then consume
                const float v0 = __ldcs(p + 0 * HW_SZ);
                const float v1 = __ldcs(p + 1 * HW_SZ);
                const float v2 = __ldcs(p + 2 * HW_SZ);
                const float v3 = __ldcs(p + 3 * HW_SZ);
                const float v4 = __ldcs(p + 4 * HW_SZ);
                const float v5 = __ldcs(p + 5 * HW_SZ);
                const float v6 = __ldcs(p + 6 * HW_SZ);
                const float v7 = __ldcs(p + 7 * HW_SZ);
                p += 8 * HW_SZ;
                a0 += __expf(v0);
                a1 += __expf(v1);
                a2 += __expf(v2);
                a3 += __expf(v3);
                a0 += __expf(v4);
                a1 += __expf(v5);
                a2 += __expf(v6);
                a3 += __expf(v7);
            }
        }
        sm_s[w][lane] = (a0 + a1) + (a2 + a3);
        __syncthreads();
    } else {
        // ---- chain warp (w=16): parent-chain walk, overlapped ----
        float child_lp   = 0.f;   // self-contained child-group log-probs
        float root_logit = 0.f;   // group-0 logits on the chain
        float root_cnt   = 0.f;   // # group-0 terms (each needs lse0)

        int cur = valid ? label[pos] : -1;
        #pragma unroll 1
        for (int d = 0; d < 8; d++) {            // MAX_DEPTH = 8
            if (!__ballot_sync(0xffffffffu, cur >= 0)) break;
            if (cur >= 0) {
                const int g = cid_groups[cur];
                if (g == 0) {
                    root_logit += base[cur * HW_SZ];
                    root_cnt   += 1.f;
                } else {
                    const int go = group_offsets[g];
                    const int gs = group_sizes[g];   // 7
                    float ss = 0.f, xv = 0.f;
                    for (int j = 0; j < gs; j++) {
                        const float v = base[(go + j) * HW_SZ];
                        ss += __expf(v);
                        if (go + j == cur) xv = v;
                    }
                    child_lp += xv - __logf(ss);
                }
                cur = parents[cur];
            }
        }

        __syncthreads();

        // merge the 16 streaming partials for this position
        float S = 0.f;
        #pragma unroll
        for (int q = 0; q < NW_STREAM; q++) S += sm_s[q][lane];

        float loss = 0.f;
        if (valid)
            loss = -(child_lp + root_logit - root_cnt * __logf(S));

        #pragma unroll
        for (int o = 16; o; o >>= 1)
            loss += __shfl_xor_sync(0xffffffffu, loss, o);
        if (lane == 0)
            atomicAdd(out, loss * inv_norm);
    }
}

extern "C" void kernel_launch(void* const* d_in, const int* in_sizes, int n_in,
                              void* d_out, int out_size)
{
    const float* x     = (const float*)d_in[0];
    const int* label   = (const int*)d_in[1];
    const int* g_off   = (const int*)d_in[2];
    const int* g_sz    = (const int*)d_in[3];
    const int* cid     = (const int*)d_in[4];
    const int* par     = (const int*)d_in[5];
    float* out         = (float*)d_out;

    const int M = in_sizes[1];          // N*H*W (label element count)
    const int N = M / HW_SZ;            // batch size for normalization
    const float inv_norm = 1.0f / (float)N;

    cudaMemsetAsync(d_out, 0, sizeof(float));

    const int blocks = (M + POS_PER_BLOCK - 1) / POS_PER_BLOCK;
    tree_loss_kernel<<<blocks, THREADS>>>(x, label, g_off, g_sz, cid, par,
                                          out, M, inv_norm);
}